// round 12
// baseline (speedup 1.0000x reference)
#include <cuda_runtime.h>
#include <cuda_fp16.h>
#include <cstdint>

// GraphAttentionLayer: out = softmax(leaky_relu(Wh @ Wh^T)) @ Wh, Wh = h @ W
// N=8192, DIN=256, D=128. Flash attention on warp-level HMMA, cp.async
// double-buffered tiles. QK^T in fp16 with fp16 accumulation (2x MMA rate;
// safe: softmax winner weight is exp(0)=1 exactly, losers ~e^-60). PV in
// fp16 inputs with fp32 accumulation (V quantization ~2e-4 rel = dominant
// output error, 5x under the 1e-3 threshold). Split-K=2 + combine.

#define NN 8192
#define DIN 256
#define D 128
#define BM 128          // query rows per CTA (16 per warp, 8 warps)
#define BN 64           // key rows per tile
#define SPLIT 2
#define KT_PER (NN / BN / SPLIT)   // 64 key tiles per CTA
#define NEG_SLOPE 0.2f

// ---------------- device scratch (no allocations allowed) ----------------
__device__ __align__(16) __half g_Kf[NN * D];        // fp16 Wh (Q and K)
__device__ __align__(16) __half g_VT[D * NN];        // V^T fp16 (dim-major)
__device__ __align__(16) float  g_Opart[SPLIT * NN * D];
__device__ float g_m[SPLIT * NN];
__device__ float g_l[SPLIT * NN];

// ---------------- warp-MMA / async-copy helpers (portable PTX) ----------------
__device__ __forceinline__ uint32_t smem_u32(const void* p) {
    uint32_t a;
    asm("{ .reg .u64 t; cvta.to.shared.u64 t, %1; cvt.u32.u64 %0, t; }" : "=r"(a) : "l"(p));
    return a;
}
__device__ __forceinline__ void ldsm4(uint32_t r[4], uint32_t addr) {
    asm volatile("ldmatrix.sync.aligned.m8n8.x4.shared.b16 {%0,%1,%2,%3}, [%4];"
                 : "=r"(r[0]), "=r"(r[1]), "=r"(r[2]), "=r"(r[3]) : "r"(addr));
}
// fp16 inputs, fp16 accumulators (2 b32 regs = 4 halfs) — 2x rate
__device__ __forceinline__ void mma_f16acc(uint32_t d[2], const uint32_t a[4],
                                           uint32_t b0, uint32_t b1) {
    asm volatile("mma.sync.aligned.m16n8k16.row.col.f16.f16.f16.f16 "
                 "{%0,%1}, {%2,%3,%4,%5}, {%6,%7}, {%0,%1};"
                 : "+r"(d[0]), "+r"(d[1])
                 : "r"(a[0]), "r"(a[1]), "r"(a[2]), "r"(a[3]), "r"(b0), "r"(b1));
}
// fp16 inputs, fp32 accumulators
__device__ __forceinline__ void mma_f16(float d[4], const uint32_t a[4],
                                        uint32_t b0, uint32_t b1) {
    asm volatile("mma.sync.aligned.m16n8k16.row.col.f32.f16.f16.f32 "
                 "{%0,%1,%2,%3}, {%4,%5,%6,%7}, {%8,%9}, {%0,%1,%2,%3};"
                 : "+f"(d[0]), "+f"(d[1]), "+f"(d[2]), "+f"(d[3])
                 : "r"(a[0]), "r"(a[1]), "r"(a[2]), "r"(a[3]), "r"(b0), "r"(b1));
}
__device__ __forceinline__ uint32_t pack_f16x2(float lo, float hi) {
    uint32_t r;
    asm("cvt.rn.f16x2.f32 %0, %1, %2;" : "=r"(r) : "f"(hi), "f"(lo));
    return r;
}
__device__ __forceinline__ void cp16(uint32_t dst, const void* src) {
    asm volatile("cp.async.cg.shared.global [%0], [%1], 16;" :: "r"(dst), "l"(src) : "memory");
}
#define CP_COMMIT()  asm volatile("cp.async.commit_group;" ::: "memory")
#define CP_WAIT0()   asm volatile("cp.async.wait_group 0;" ::: "memory")

// SMEM layout (dynamic, 98304 B) for attn:
//   Q: 32 KB (persistent). Two 32 KB buffers, each K(16K) + VT(16K).
#define SM_Q       0
#define SM_BUF     32768
#define BUF_STRIDE 32768
#define BUF_K      0
#define BUF_VT     16384
#define SM_TOTAL   98304

// ---------------------------------------------------------------------------
// Kernel 1: Wh = h @ W (fp32 accum). 32-row tiles, h staged transposed in
// smem (broadcast-friendly), fused fp16 outputs:
//   g_Kf = fp16 Wh (row-major, coalesced 2B stores across d)
//   g_VT = fp16 Wh^T (dim-major; 2x16B contiguous stores per thread)
// ---------------------------------------------------------------------------
__global__ __launch_bounds__(256) void wh_kernel(const float* __restrict__ h,
                                                 const float* __restrict__ W) {
    __shared__ float hs[DIN][36];       // [k][row], pad 36 keeps 16B alignment
    const int r0 = blockIdx.x * 32;
    const int tid = threadIdx.x;
    const int d = tid & 127;            // output column
    const int roff = (tid >> 7) * 16;   // row group: 0 or 16

    // stage h rows r0..r0+31 transposed
    for (int i = tid; i < 32 * DIN / 4; i += 256) {
        int c4 = i * 4;
        int row = c4 >> 8;              // c4 / DIN
        int col = c4 & 255;             // c4 % DIN
        float4 v = *(const float4*)&h[(size_t)(r0 + row) * DIN + col];
        hs[col + 0][row] = v.x;
        hs[col + 1][row] = v.y;
        hs[col + 2][row] = v.z;
        hs[col + 3][row] = v.w;
    }
    __syncthreads();

    float acc[16];
#pragma unroll
    for (int r = 0; r < 16; r++) acc[r] = 0.f;

    for (int k = 0; k < DIN; k++) {
        float w = W[k * D + d];
        float4 a0 = *(float4*)&hs[k][roff + 0];
        float4 a1 = *(float4*)&hs[k][roff + 4];
        float4 a2 = *(float4*)&hs[k][roff + 8];
        float4 a3 = *(float4*)&hs[k][roff + 12];
        acc[0]  = fmaf(a0.x, w, acc[0]);  acc[1]  = fmaf(a0.y, w, acc[1]);
        acc[2]  = fmaf(a0.z, w, acc[2]);  acc[3]  = fmaf(a0.w, w, acc[3]);
        acc[4]  = fmaf(a1.x, w, acc[4]);  acc[5]  = fmaf(a1.y, w, acc[5]);
        acc[6]  = fmaf(a1.z, w, acc[6]);  acc[7]  = fmaf(a1.w, w, acc[7]);
        acc[8]  = fmaf(a2.x, w, acc[8]);  acc[9]  = fmaf(a2.y, w, acc[9]);
        acc[10] = fmaf(a2.z, w, acc[10]); acc[11] = fmaf(a2.w, w, acc[11]);
        acc[12] = fmaf(a3.x, w, acc[12]); acc[13] = fmaf(a3.y, w, acc[13]);
        acc[14] = fmaf(a3.z, w, acc[14]); acc[15] = fmaf(a3.w, w, acc[15]);
    }

    // row-major fp16 (coalesced across d)
#pragma unroll
    for (int r = 0; r < 16; r++)
        g_Kf[(size_t)(r0 + roff + r) * D + d] = __float2half_rn(acc[r]);

    // transposed fp16: 16 consecutive n-values = 32 contiguous bytes
    __half2 pk[8];
#pragma unroll
    for (int i = 0; i < 8; i++) pk[i] = __floats2half2_rn(acc[2 * i], acc[2 * i + 1]);
    *(uint4*)&g_VT[(size_t)d * NN + r0 + roff + 0] = *(uint4*)&pk[0];
    *(uint4*)&g_VT[(size_t)d * NN + r0 + roff + 8] = *(uint4*)&pk[4];
}

// ---------------------------------------------------------------------------
// Async prefetch of one K/VT tile set into buffer `buf` (swizzled layout).
// ---------------------------------------------------------------------------
__device__ __forceinline__ void prefetch_tile(uint32_t sbase, int buf, int key0, int tid) {
    const uint32_t base = sbase + SM_BUF + buf * BUF_STRIDE;
#pragma unroll
    for (int it = 0; it < 4; it++) {                  // K: 64 rows x 16 chunks
        int i = tid + it * 256;
        int row = i >> 4, ch = i & 15;
        cp16(base + BUF_K + row * 256 + ((ch ^ (row & 7)) << 4),
             g_Kf + (size_t)(key0 + row) * D + ch * 8);
    }
#pragma unroll
    for (int it = 0; it < 4; it++) {                  // VT: 128 rows x 8 chunks
        int i = tid + it * 256;
        int row = i >> 3, ch = i & 7;
        cp16(base + BUF_VT + (uint32_t)(row * 128 + ((ch ^ (row & 7)) << 4)),
             g_VT + (size_t)row * NN + key0 + ch * 8);
    }
    CP_COMMIT();
}

// ---------------------------------------------------------------------------
// Kernel 2: flash attention, warp HMMA + cp.async double buffering.
// grid (64, SPLIT), 256 threads. Warp w owns query rows q0+16w..+15.
// Fragment layouts (mma.m16n8k16): per thread,
//   A: a0=(r,k2) a1=(r+8,k2) a2=(r,k2+8) a3=(r+8,k2+8), r=lane>>2, k2=2*(lane&3)
//   B: b0=(k2,n) b1=(k2+8,n), n=lane>>2
//   C fp32: c0,c1=(r, 2n..+1)  c2,c3=(r+8, 2n..+1)
//   C fp16: reg0={ (r,2n),(r,2n+1) }  reg1={ (r+8,2n),(r+8,2n+1) }
// ---------------------------------------------------------------------------
__global__ __launch_bounds__(256, 1) void attn_kernel() {
    extern __shared__ char smem[];
    const uint32_t sbase = smem_u32(smem);
    const int tid = threadIdx.x;
    const int wid = tid >> 5;
    const int lane = tid & 31;
    const int q0 = blockIdx.x * BM;
    const int split = blockIdx.y;
    const int key_base = split * (NN / SPLIT);

    // ---- kick off prefetch of tile 0 immediately ----
    prefetch_tile(sbase, 0, key_base, tid);

    // ---- load Q tile into smem (swizzled), regular stores ----
    for (int i = tid; i < 2048; i += 256) {           // 128 rows x 16 chunks
        int row = i >> 4, ch = i & 15;
        const uint4 v = *(const uint4*)(g_Kf + (size_t)(q0 + row) * D + ch * 8);
        *(uint4*)(smem + SM_Q + row * 256 + ((ch ^ (row & 7)) << 4)) = v;
    }
    __syncthreads();

    // ---- Q fragments into registers (held for whole kernel) ----
    uint32_t qf[8][4];
    {
        int arow = 16 * wid + (lane & 15);
        int achb = lane >> 4;
#pragma unroll
        for (int k = 0; k < 8; k++) {
            int ch = 2 * k + achb;
            uint32_t addr = sbase + SM_Q + arow * 256 + ((ch ^ (arow & 7)) << 4);
            ldsm4(qf[k], addr);
        }
    }

    // B-fragment ldmatrix lane addressing:
    // lane l -> row = n0 + ((l>>4)<<3) + (l&7), chunk = 2k + ((l>>3)&1)
    const int brow_off = ((lane >> 4) << 3) + (lane & 7);
    const int bch_off = (lane >> 3) & 1;

    float o[16][4];
#pragma unroll
    for (int n = 0; n < 16; n++)
#pragma unroll
        for (int j = 0; j < 4; j++) o[n][j] = 0.f;
    float m0r = -1e30f, m1r = -1e30f, l0r = 0.f, l1r = 0.f;

    for (int kt = 0; kt < KT_PER; kt++) {
        // tile kt data ready; all warps past their reads of the other buffer
        CP_WAIT0();
        __syncthreads();

        const uint32_t bufb = sbase + SM_BUF + (kt & 1) * BUF_STRIDE;

        // ---- S = Q @ K^T : 8 ntiles (n8) x 8 ktiles (k16), fp16 accum ----
        uint32_t sacc[8][2];
#pragma unroll
        for (int n = 0; n < 8; n++) { sacc[n][0] = 0u; sacc[n][1] = 0u; }
#pragma unroll
        for (int np = 0; np < 4; np++) {              // pair of n8 tiles
            int brow = 16 * np + brow_off;
            uint32_t rbase = bufb + BUF_K + brow * 256;
            int bsw = brow & 7;
#pragma unroll
            for (int k = 0; k < 8; k++) {
                int ch = 2 * k + bch_off;
                uint32_t b[4];
                ldsm4(b, rbase + ((ch ^ bsw) << 4));
                mma_f16acc(sacc[2 * np], qf[k], b[0], b[1]);
                mma_f16acc(sacc[2 * np + 1], qf[k], b[2], b[3]);
            }
        }

        // prefetch next tile (issued after MMAs so it doesn't delay them;
        // latency hidden by softmax + PV below)
        if (kt + 1 < KT_PER)
            prefetch_tile(sbase, (kt + 1) & 1, key_base + (kt + 1) * BN, tid);

        // ---- unpack S to fp32 ----
        float s[8][4];
#pragma unroll
        for (int n = 0; n < 8; n++) {
            float2 x = __half22float2(*(__half2*)&sacc[n][0]);
            float2 y = __half22float2(*(__half2*)&sacc[n][1]);
            s[n][0] = x.x; s[n][1] = x.y; s[n][2] = y.x; s[n][3] = y.y;
        }

        // ---- leaky_relu + online softmax (rows r=lane>>2 and r+8) ----
#pragma unroll
        for (int n = 0; n < 8; n++)
#pragma unroll
            for (int j = 0; j < 4; j++)
                s[n][j] = fmaxf(s[n][j], NEG_SLOPE * s[n][j]);

        float mx0 = -1e30f, mx1 = -1e30f;
#pragma unroll
        for (int n = 0; n < 8; n++) {
            mx0 = fmaxf(mx0, fmaxf(s[n][0], s[n][1]));
            mx1 = fmaxf(mx1, fmaxf(s[n][2], s[n][3]));
        }
        mx0 = fmaxf(mx0, __shfl_xor_sync(0xffffffffu, mx0, 1));
        mx0 = fmaxf(mx0, __shfl_xor_sync(0xffffffffu, mx0, 2));
        mx1 = fmaxf(mx1, __shfl_xor_sync(0xffffffffu, mx1, 1));
        mx1 = fmaxf(mx1, __shfl_xor_sync(0xffffffffu, mx1, 2));

        float mn0 = fmaxf(m0r, mx0), mn1 = fmaxf(m1r, mx1);
        float a0 = __expf(m0r - mn0), a1 = __expf(m1r - mn1);
        m0r = mn0; m1r = mn1;

        // lazy rescale of O (running max rarely grows for peaked softmax)
        if (kt > 0) {
            unsigned need = __ballot_sync(0xffffffffu, (a0 != 1.f) || (a1 != 1.f));
            if (need) {
#pragma unroll
                for (int n = 0; n < 16; n++) {
                    o[n][0] *= a0; o[n][1] *= a0;
                    o[n][2] *= a1; o[n][3] *= a1;
                }
            }
        }

        float ps0 = 0.f, ps1 = 0.f;
#pragma unroll
        for (int n = 0; n < 8; n++) {
            s[n][0] = __expf(s[n][0] - mn0);
            s[n][1] = __expf(s[n][1] - mn0);
            s[n][2] = __expf(s[n][2] - mn1);
            s[n][3] = __expf(s[n][3] - mn1);
            ps0 += s[n][0] + s[n][1];
            ps1 += s[n][2] + s[n][3];
        }
        ps0 += __shfl_xor_sync(0xffffffffu, ps0, 1);
        ps0 += __shfl_xor_sync(0xffffffffu, ps0, 2);
        ps1 += __shfl_xor_sync(0xffffffffu, ps1, 1);
        ps1 += __shfl_xor_sync(0xffffffffu, ps1, 2);
        l0r = l0r * a0 + ps0;
        l1r = l1r * a1 + ps1;

        // ---- P fragments: S accum frag -> A operand frag (fp16) ----
        uint32_t pA[4][4];    // 4 k16-tiles over seq(=BN), A layout
#pragma unroll
        for (int j = 0; j < 4; j++) {
            pA[j][0] = pack_f16x2(s[2 * j][0], s[2 * j][1]);
            pA[j][1] = pack_f16x2(s[2 * j][2], s[2 * j][3]);
            pA[j][2] = pack_f16x2(s[2 * j + 1][0], s[2 * j + 1][1]);
            pA[j][3] = pack_f16x2(s[2 * j + 1][2], s[2 * j + 1][3]);
        }

        // ---- O += P @ V^T : 8 npairs (d) x 4 ktiles (seq), fp32 accum ----
#pragma unroll
        for (int np = 0; np < 8; np++) {
            int brow = 16 * np + brow_off;
            int bsw = brow & 7;
            uint32_t rv = bufb + BUF_VT + brow * 128;
#pragma unroll
            for (int j = 0; j < 4; j++) {
                int ch = 2 * j + bch_off;
                uint32_t b[4];
                ldsm4(b, rv + (uint32_t)((ch ^ bsw) << 4));
                mma_f16(o[2 * np], pA[j], b[0], b[1]);
                mma_f16(o[2 * np + 1], pA[j], b[2], b[3]);
            }
        }
        // (no end-of-loop barrier: the top-of-loop barrier in iteration kt+1
        //  orders all warps' reads of this buffer before kt+2's prefetch hits it)
    }

    // ---- epilogue: dump unnormalized O + (m, l) partials ----
    const int r0 = q0 + 16 * wid + (lane >> 2);
    const int cb = 2 * (lane & 3);
    float* ob = &g_Opart[((size_t)split * NN + r0) * D];
#pragma unroll
    for (int n = 0; n < 16; n++) {
        *(float2*)&ob[8 * n + cb] = make_float2(o[n][0], o[n][1]);
        *(float2*)&ob[8 * D + 8 * n + cb] = make_float2(o[n][2], o[n][3]);  // row r0+8
    }
    if ((lane & 3) == 0) {
        g_m[split * NN + r0] = m0r;
        g_l[split * NN + r0] = l0r;
        g_m[split * NN + r0 + 8] = m1r;
        g_l[split * NN + r0 + 8] = l1r;
    }
}

// ---------------------------------------------------------------------------
// Kernel 3: combine the SPLIT partials
// ---------------------------------------------------------------------------
__global__ __launch_bounds__(128) void combine_kernel(float* __restrict__ out) {
    const int r = blockIdx.x, c = threadIdx.x;
    float m0 = g_m[r], m1 = g_m[NN + r];
    float m = fmaxf(m0, m1);
    float w0 = __expf(m0 - m), w1 = __expf(m1 - m);
    float l = g_l[r] * w0 + g_l[NN + r] * w1;
    float o = g_Opart[(size_t)r * D + c] * w0 + g_Opart[(size_t)(NN + r) * D + c] * w1;
    out[(size_t)r * D + c] = o / l;
}

// ---------------------------------------------------------------------------
extern "C" void kernel_launch(void* const* d_in, const int* in_sizes, int n_in,
                              void* d_out, int out_size) {
    const float* h = (const float*)d_in[0];
    // d_in[1] = adj: unused by the math, never touched
    const float* W = (const float*)d_in[2];
    float* out = (float*)d_out;

    cudaFuncSetAttribute(attn_kernel, cudaFuncAttributeMaxDynamicSharedMemorySize, SM_TOTAL);

    wh_kernel<<<NN / 32, 256>>>(h, W);
    attn_kernel<<<dim3(NN / BM, SPLIT), 256, SM_TOTAL>>>();
    combine_kernel<<<NN, 128>>>(out);
}

// round 14
// speedup vs baseline: 1.0671x; 1.0671x over previous
#include <cuda_runtime.h>
#include <cuda_fp16.h>
#include <cstdint>

// GraphAttentionLayer: out = softmax(leaky_relu(Wh @ Wh^T)) @ Wh, Wh = h @ W
// N=8192, DIN=256, D=128. Wh computed on HMMA via hi/lo fp16 split of both
// operands (3 cross-terms -> fp32-grade product). Flash attention on warp
// HMMA with cp.async double buffering: QK^T fp16-acc, PV fp16-in/fp32-acc.
// V fp16 quantization (~2e-4) is the dominant output error. Split-K=2.

#define NN 8192
#define DIN 256
#define D 128
#define BM 128          // query rows per CTA (16 per warp, 8 warps)
#define BN 64           // key rows per tile
#define SPLIT 2
#define KT_PER (NN / BN / SPLIT)   // 64 key tiles per CTA
#define KC 64           // wh GEMM k-chunk
#define NKC (DIN / KC)  // 4
#define NEG_SLOPE 0.2f

// ---------------- device scratch (no allocations allowed) ----------------
__device__ __align__(16) __half g_hhi[NN * DIN];     // h hi fp16
__device__ __align__(16) __half g_hlo[NN * DIN];     // h lo fp16
__device__ __align__(16) __half g_WThi[D * DIN];     // W^T hi fp16 [n][k]
__device__ __align__(16) __half g_WTlo[D * DIN];     // W^T lo fp16
__device__ __align__(16) __half g_Kf[NN * D];        // fp16 Wh (Q and K)
__device__ __align__(16) __half g_VT[D * NN];        // V^T fp16 (dim-major)
__device__ __align__(16) float  g_Opart[SPLIT * NN * D];
__device__ float g_m[SPLIT * NN];
__device__ float g_l[SPLIT * NN];

// ---------------- warp-MMA / async-copy helpers (portable PTX) ----------------
__device__ __forceinline__ uint32_t smem_u32(const void* p) {
    uint32_t a;
    asm("{ .reg .u64 t; cvta.to.shared.u64 t, %1; cvt.u32.u64 %0, t; }" : "=r"(a) : "l"(p));
    return a;
}
__device__ __forceinline__ void ldsm4(uint32_t r[4], uint32_t addr) {
    asm volatile("ldmatrix.sync.aligned.m8n8.x4.shared.b16 {%0,%1,%2,%3}, [%4];"
                 : "=r"(r[0]), "=r"(r[1]), "=r"(r[2]), "=r"(r[3]) : "r"(addr));
}
// fp16 inputs, fp16 accumulators — 2x rate (QK^T)
__device__ __forceinline__ void mma_f16acc(uint32_t d[2], const uint32_t a[4],
                                           uint32_t b0, uint32_t b1) {
    asm volatile("mma.sync.aligned.m16n8k16.row.col.f16.f16.f16.f16 "
                 "{%0,%1}, {%2,%3,%4,%5}, {%6,%7}, {%0,%1};"
                 : "+r"(d[0]), "+r"(d[1])
                 : "r"(a[0]), "r"(a[1]), "r"(a[2]), "r"(a[3]), "r"(b0), "r"(b1));
}
// fp16 inputs, fp32 accumulators (PV, wh)
__device__ __forceinline__ void mma_f16(float d[4], const uint32_t a[4],
                                        uint32_t b0, uint32_t b1) {
    asm volatile("mma.sync.aligned.m16n8k16.row.col.f32.f16.f16.f32 "
                 "{%0,%1,%2,%3}, {%4,%5,%6,%7}, {%8,%9}, {%0,%1,%2,%3};"
                 : "+f"(d[0]), "+f"(d[1]), "+f"(d[2]), "+f"(d[3])
                 : "r"(a[0]), "r"(a[1]), "r"(a[2]), "r"(a[3]), "r"(b0), "r"(b1));
}
__device__ __forceinline__ uint32_t pack_f16x2(float lo, float hi) {
    uint32_t r;
    asm("cvt.rn.f16x2.f32 %0, %1, %2;" : "=r"(r) : "f"(hi), "f"(lo));
    return r;
}
__device__ __forceinline__ void cp16(uint32_t dst, const void* src) {
    asm volatile("cp.async.cg.shared.global [%0], [%1], 16;" :: "r"(dst), "l"(src) : "memory");
}
#define CP_COMMIT()  asm volatile("cp.async.commit_group;" ::: "memory")
#define CP_WAIT0()   asm volatile("cp.async.wait_group 0;" ::: "memory")

// attn SMEM (dynamic, 98304 B): Q 32K persistent + two 32K buffers (K+VT)
#define SM_Q       0
#define SM_BUF     32768
#define BUF_STRIDE 32768
#define BUF_K      0
#define BUF_VT     16384
#define SM_TOTAL   98304
// wh GEMM SMEM (dynamic, 131072 B): two stages of Ahi/Alo/Bhi/Blo (16K each)
#define WH_STAGE   65536
#define WH_AHI     0
#define WH_ALO     16384
#define WH_BHI     32768
#define WH_BLO     49152
#define WH_SM_TOTAL 131072

// ---------------------------------------------------------------------------
// Kernel 1a: h -> hi/lo fp16 (element-wise)
// ---------------------------------------------------------------------------
__global__ __launch_bounds__(256) void hconv_kernel(const float* __restrict__ h) {
    size_t i = ((size_t)blockIdx.x * 256 + threadIdx.x) * 4;
    float4 v = *(const float4*)&h[i];
    __half hi[4], lo[4];
    float f[4] = {v.x, v.y, v.z, v.w};
#pragma unroll
    for (int j = 0; j < 4; j++) {
        hi[j] = __float2half_rn(f[j]);
        lo[j] = __float2half_rn(f[j] - __half2float(hi[j]));
    }
    *(uint2*)&g_hhi[i] = *(uint2*)hi;
    *(uint2*)&g_hlo[i] = *(uint2*)lo;
}

// ---------------------------------------------------------------------------
// Kernel 1b: W[k][n] -> W^T hi/lo fp16 [n][k]
// ---------------------------------------------------------------------------
__global__ __launch_bounds__(256) void wconv_kernel(const float* __restrict__ W) {
    __shared__ float ts[32][33];
    const int k0 = blockIdx.x * 32;   // over DIN
    const int n0 = blockIdx.y * 32;   // over D
    const int tx = threadIdx.x, ty = threadIdx.y;   // 32 x 8
    for (int r = ty; r < 32; r += 8) ts[r][tx] = W[(size_t)(k0 + r) * D + n0 + tx];
    __syncthreads();
    for (int nn = ty; nn < 32; nn += 8) {
        float v = ts[tx][nn];         // = W[k0+tx][n0+nn]
        __half hi = __float2half_rn(v);
        __half lo = __float2half_rn(v - __half2float(hi));
        g_WThi[(size_t)(n0 + nn) * DIN + k0 + tx] = hi;
        g_WTlo[(size_t)(n0 + nn) * DIN + k0 + tx] = lo;
    }
}

// ---------------------------------------------------------------------------
// wh GEMM prefetch: one k-chunk of A(h) hi/lo [128rx64k] + B(W^T) hi/lo
// [128nx64k], 128B swizzled rows.
// ---------------------------------------------------------------------------
__device__ __forceinline__ void wh_prefetch(uint32_t sbase, int buf, int r0, int kc, int tid) {
    const uint32_t base = sbase + buf * WH_STAGE;
    const int k0 = kc * KC;
#pragma unroll
    for (int it = 0; it < 4; it++) {
        int i = tid + it * 256;
        int row = i >> 3, ch = i & 7;
        uint32_t soff = (uint32_t)(row * 128 + ((ch ^ (row & 7)) << 4));
        size_t ga = (size_t)(r0 + row) * DIN + k0 + ch * 8;
        cp16(base + WH_AHI + soff, g_hhi + ga);
        cp16(base + WH_ALO + soff, g_hlo + ga);
        size_t gb = (size_t)row * DIN + k0 + ch * 8;
        cp16(base + WH_BHI + soff, g_WThi + gb);
        cp16(base + WH_BLO + soff, g_WTlo + gb);
    }
    CP_COMMIT();
}

// ---------------------------------------------------------------------------
// Kernel 1c: Wh = h @ W on HMMA, hi/lo 3-term (fp32-grade). 64 CTAs x 128 rows.
// Outputs g_Kf (row-major fp16) and g_VT (transposed fp16).
// ---------------------------------------------------------------------------
__global__ __launch_bounds__(256, 1) void whtc_kernel() {
    extern __shared__ char smem[];
    const uint32_t sbase = smem_u32(smem);
    const int tid = threadIdx.x;
    const int wid = tid >> 5;
    const int lane = tid & 31;
    const int r0 = blockIdx.x * 128;

    wh_prefetch(sbase, 0, r0, 0, tid);

    const int arow = 16 * wid + (lane & 15);
    const int achb = lane >> 4;
    const int asw = arow & 7;
    const int brow_off = ((lane >> 4) << 3) + (lane & 7);
    const int bch_off = (lane >> 3) & 1;

    float o[16][4];
#pragma unroll
    for (int n = 0; n < 16; n++)
#pragma unroll
        for (int j = 0; j < 4; j++) o[n][j] = 0.f;

    for (int kc = 0; kc < NKC; kc++) {
        CP_WAIT0();
        __syncthreads();
        if (kc + 1 < NKC) wh_prefetch(sbase, (kc + 1) & 1, r0, kc + 1, tid);

        const uint32_t sb = sbase + (kc & 1) * WH_STAGE;
        uint32_t ahi[4][4], alo[4][4];
#pragma unroll
        for (int kt = 0; kt < 4; kt++) {
            int ch = 2 * kt + achb;
            ldsm4(ahi[kt], sb + WH_AHI + arow * 128 + ((ch ^ asw) << 4));
            ldsm4(alo[kt], sb + WH_ALO + arow * 128 + ((ch ^ asw) << 4));
        }
#pragma unroll
        for (int np = 0; np < 8; np++) {
            int brow = 16 * np + brow_off;
            int bsw = brow & 7;
            uint32_t rbh = sb + WH_BHI + brow * 128;
            uint32_t rbl = sb + WH_BLO + brow * 128;
#pragma unroll
            for (int kt = 0; kt < 4; kt++) {
                int ch = 2 * kt + bch_off;
                uint32_t sw = (uint32_t)((ch ^ bsw) << 4);
                uint32_t b[4];
                ldsm4(b, rbh + sw);
                mma_f16(o[2 * np], ahi[kt], b[0], b[1]);
                mma_f16(o[2 * np + 1], ahi[kt], b[2], b[3]);
                mma_f16(o[2 * np], alo[kt], b[0], b[1]);
                mma_f16(o[2 * np + 1], alo[kt], b[2], b[3]);
                ldsm4(b, rbl + sw);
                mma_f16(o[2 * np], ahi[kt], b[0], b[1]);
                mma_f16(o[2 * np + 1], ahi[kt], b[2], b[3]);
            }
        }
        // no end barrier: next iteration's top barrier orders reads before the
        // prefetch two chunks ahead overwrites this stage
    }

    // epilogue: rows r0+16w+(lane>>2)(+8), cols 8n+2(lane&3)(+1)
    const int row = r0 + 16 * wid + (lane >> 2);
    const int cb = 2 * (lane & 3);
#pragma unroll
    for (int n = 0; n < 16; n++) {
        int c = 8 * n + cb;
        __half2 h0 = __floats2half2_rn(o[n][0], o[n][1]);
        __half2 h1 = __floats2half2_rn(o[n][2], o[n][3]);
        *(__half2*)&g_Kf[(size_t)row * D + c] = h0;
        *(__half2*)&g_Kf[(size_t)(row + 8) * D + c] = h1;
        g_VT[(size_t)c * NN + row] = __low2half(h0);
        g_VT[(size_t)(c + 1) * NN + row] = __high2half(h0);
        g_VT[(size_t)c * NN + row + 8] = __low2half(h1);
        g_VT[(size_t)(c + 1) * NN + row + 8] = __high2half(h1);
    }
}

// ---------------------------------------------------------------------------
// attn prefetch: one K/VT tile set (swizzled)
// ---------------------------------------------------------------------------
__device__ __forceinline__ void prefetch_tile(uint32_t sbase, int buf, int key0, int tid) {
    const uint32_t base = sbase + SM_BUF + buf * BUF_STRIDE;
#pragma unroll
    for (int it = 0; it < 4; it++) {                  // K: 64 rows x 16 chunks
        int i = tid + it * 256;
        int row = i >> 4, ch = i & 15;
        cp16(base + BUF_K + row * 256 + ((ch ^ (row & 7)) << 4),
             g_Kf + (size_t)(key0 + row) * D + ch * 8);
    }
#pragma unroll
    for (int it = 0; it < 4; it++) {                  // VT: 128 rows x 8 chunks
        int i = tid + it * 256;
        int row = i >> 3, ch = i & 7;
        cp16(base + BUF_VT + (uint32_t)(row * 128 + ((ch ^ (row & 7)) << 4)),
             g_VT + (size_t)row * NN + key0 + ch * 8);
    }
    CP_COMMIT();
}

// ---------------------------------------------------------------------------
// Kernel 2: flash attention (unchanged from R11 best-attn config)
// ---------------------------------------------------------------------------
__global__ __launch_bounds__(256, 1) void attn_kernel() {
    extern __shared__ char smem[];
    const uint32_t sbase = smem_u32(smem);
    const int tid = threadIdx.x;
    const int wid = tid >> 5;
    const int lane = tid & 31;
    const int q0 = blockIdx.x * BM;
    const int split = blockIdx.y;
    const int key_base = split * (NN / SPLIT);

    prefetch_tile(sbase, 0, key_base, tid);

    for (int i = tid; i < 2048; i += 256) {           // Q: 128 rows x 16 chunks
        int row = i >> 4, ch = i & 15;
        const uint4 v = *(const uint4*)(g_Kf + (size_t)(q0 + row) * D + ch * 8);
        *(uint4*)(smem + SM_Q + row * 256 + ((ch ^ (row & 7)) << 4)) = v;
    }
    __syncthreads();

    uint32_t qf[8][4];
    {
        int arow = 16 * wid + (lane & 15);
        int achb = lane >> 4;
#pragma unroll
        for (int k = 0; k < 8; k++) {
            int ch = 2 * k + achb;
            ldsm4(qf[k], sbase + SM_Q + arow * 256 + ((ch ^ (arow & 7)) << 4));
        }
    }

    const int brow_off = ((lane >> 4) << 3) + (lane & 7);
    const int bch_off = (lane >> 3) & 1;

    float o[16][4];
#pragma unroll
    for (int n = 0; n < 16; n++)
#pragma unroll
        for (int j = 0; j < 4; j++) o[n][j] = 0.f;
    float m0r = -1e30f, m1r = -1e30f, l0r = 0.f, l1r = 0.f;

    for (int kt = 0; kt < KT_PER; kt++) {
        CP_WAIT0();
        __syncthreads();

        const uint32_t bufb = sbase + SM_BUF + (kt & 1) * BUF_STRIDE;

        uint32_t sacc[8][2];
#pragma unroll
        for (int n = 0; n < 8; n++) { sacc[n][0] = 0u; sacc[n][1] = 0u; }
#pragma unroll
        for (int np = 0; np < 4; np++) {
            int brow = 16 * np + brow_off;
            uint32_t rbase = bufb + BUF_K + brow * 256;
            int bsw = brow & 7;
#pragma unroll
            for (int k = 0; k < 8; k++) {
                int ch = 2 * k + bch_off;
                uint32_t b[4];
                ldsm4(b, rbase + ((ch ^ bsw) << 4));
                mma_f16acc(sacc[2 * np], qf[k], b[0], b[1]);
                mma_f16acc(sacc[2 * np + 1], qf[k], b[2], b[3]);
            }
        }

        if (kt + 1 < KT_PER)
            prefetch_tile(sbase, (kt + 1) & 1, key_base + (kt + 1) * BN, tid);

        float s[8][4];
#pragma unroll
        for (int n = 0; n < 8; n++) {
            float2 x = __half22float2(*(__half2*)&sacc[n][0]);
            float2 y = __half22float2(*(__half2*)&sacc[n][1]);
            s[n][0] = x.x; s[n][1] = x.y; s[n][2] = y.x; s[n][3] = y.y;
        }

#pragma unroll
        for (int n = 0; n < 8; n++)
#pragma unroll
            for (int j = 0; j < 4; j++)
                s[n][j] = fmaxf(s[n][j], NEG_SLOPE * s[n][j]);

        float mx0 = -1e30f, mx1 = -1e30f;
#pragma unroll
        for (int n = 0; n < 8; n++) {
            mx0 = fmaxf(mx0, fmaxf(s[n][0], s[n][1]));
            mx1 = fmaxf(mx1, fmaxf(s[n][2], s[n][3]));
        }
        mx0 = fmaxf(mx0, __shfl_xor_sync(0xffffffffu, mx0, 1));
        mx0 = fmaxf(mx0, __shfl_xor_sync(0xffffffffu, mx0, 2));
        mx1 = fmaxf(mx1, __shfl_xor_sync(0xffffffffu, mx1, 1));
        mx1 = fmaxf(mx1, __shfl_xor_sync(0xffffffffu, mx1, 2));

        float mn0 = fmaxf(m0r, mx0), mn1 = fmaxf(m1r, mx1);
        float a0 = __expf(m0r - mn0), a1 = __expf(m1r - mn1);
        m0r = mn0; m1r = mn1;

        if (kt > 0) {
            unsigned need = __ballot_sync(0xffffffffu, (a0 != 1.f) || (a1 != 1.f));
            if (need) {
#pragma unroll
                for (int n = 0; n < 16; n++) {
                    o[n][0] *= a0; o[n][1] *= a0;
                    o[n][2] *= a1; o[n][3] *= a1;
                }
            }
        }

        float ps0 = 0.f, ps1 = 0.f;
#pragma unroll
        for (int n = 0; n < 8; n++) {
            s[n][0] = __expf(s[n][0] - mn0);
            s[n][1] = __expf(s[n][1] - mn0);
            s[n][2] = __expf(s[n][2] - mn1);
            s[n][3] = __expf(s[n][3] - mn1);
            ps0 += s[n][0] + s[n][1];
            ps1 += s[n][2] + s[n][3];
        }
        ps0 += __shfl_xor_sync(0xffffffffu, ps0, 1);
        ps0 += __shfl_xor_sync(0xffffffffu, ps0, 2);
        ps1 += __shfl_xor_sync(0xffffffffu, ps1, 1);
        ps1 += __shfl_xor_sync(0xffffffffu, ps1, 2);
        l0r = l0r * a0 + ps0;
        l1r = l1r * a1 + ps1;

        uint32_t pA[4][4];
#pragma unroll
        for (int j = 0; j < 4; j++) {
            pA[j][0] = pack_f16x2(s[2 * j][0], s[2 * j][1]);
            pA[j][1] = pack_f16x2(s[2 * j][2], s[2 * j][3]);
            pA[j][2] = pack_f16x2(s[2 * j + 1][0], s[2 * j + 1][1]);
            pA[j][3] = pack_f16x2(s[2 * j + 1][2], s[2 * j + 1][3]);
        }

#pragma unroll
        for (int np = 0; np < 8; np++) {
            int brow = 16 * np + brow_off;
            int bsw = brow & 7;
            uint32_t rv = bufb + BUF_VT + brow * 128;
#pragma unroll
            for (int j = 0; j < 4; j++) {
                int ch = 2 * j + bch_off;
                uint32_t b[4];
                ldsm4(b, rv + (uint32_t)((ch ^ bsw) << 4));
                mma_f16(o[2 * np], pA[j], b[0], b[1]);
                mma_f16(o[2 * np + 1], pA[j], b[2], b[3]);
            }
        }
    }

    const int r0 = q0 + 16 * wid + (lane >> 2);
    const int cb = 2 * (lane & 3);
    float* ob = &g_Opart[((size_t)split * NN + r0) * D];
#pragma unroll
    for (int n = 0; n < 16; n++) {
        *(float2*)&ob[8 * n + cb] = make_float2(o[n][0], o[n][1]);
        *(float2*)&ob[8 * D + 8 * n + cb] = make_float2(o[n][2], o[n][3]);
    }
    if ((lane & 3) == 0) {
        g_m[split * NN + r0] = m0r;
        g_l[split * NN + r0] = l0r;
        g_m[split * NN + r0 + 8] = m1r;
        g_l[split * NN + r0 + 8] = l1r;
    }
}

// ---------------------------------------------------------------------------
// Kernel 3: combine the SPLIT partials
// ---------------------------------------------------------------------------
__global__ __launch_bounds__(128) void combine_kernel(float* __restrict__ out) {
    const int r = blockIdx.x, c = threadIdx.x;
    float m0 = g_m[r], m1 = g_m[NN + r];
    float m = fmaxf(m0, m1);
    float w0 = __expf(m0 - m), w1 = __expf(m1 - m);
    float l = g_l[r] * w0 + g_l[NN + r] * w1;
    float o = g_Opart[(size_t)r * D + c] * w0 + g_Opart[(size_t)(NN + r) * D + c] * w1;
    out[(size_t)r * D + c] = o / l;
}

// ---------------------------------------------------------------------------
extern "C" void kernel_launch(void* const* d_in, const int* in_sizes, int n_in,
                              void* d_out, int out_size) {
    const float* h = (const float*)d_in[0];
    // d_in[1] = adj: unused by the math, never touched
    const float* W = (const float*)d_in[2];
    float* out = (float*)d_out;

    cudaFuncSetAttribute(attn_kernel, cudaFuncAttributeMaxDynamicSharedMemorySize, SM_TOTAL);
    cudaFuncSetAttribute(whtc_kernel, cudaFuncAttributeMaxDynamicSharedMemorySize, WH_SM_TOTAL);

    hconv_kernel<<<NN * DIN / 1024, 256>>>(h);
    wconv_kernel<<<dim3(DIN / 32, D / 32), dim3(32, 8)>>>(W);
    whtc_kernel<<<NN / 128, 256, WH_SM_TOTAL>>>();
    attn_kernel<<<dim3(NN / BM, SPLIT), 256, SM_TOTAL>>>();
    combine_kernel<<<NN, 128>>>(out);
}

// round 15
// speedup vs baseline: 1.1479x; 1.0757x over previous
#include <cuda_runtime.h>
#include <cuda_fp16.h>
#include <cstdint>

// GraphAttentionLayer: out = softmax(leaky_relu(Wh @ Wh^T)) @ Wh, Wh = h @ W
// N=8192, DIN=256, D=128. Wh on HMMA via hi/lo fp16 split (fp32-grade).
// Flash attention on warp HMMA, cp.async double buffering, QK^T fp16-acc,
// PV fp16-in/fp32-acc. BM=64 x 128 threads x 2 CTAs/SM so one CTA's MMAs
// overlap the other's softmax (tensor-pipe duty cycle). Split-K=2.

#define NN 8192
#define DIN 256
#define D 128
#define BM 64           // query rows per CTA (16 per warp, 4 warps)
#define BN 64           // key rows per tile
#define SPLIT 2
#define KT_PER (NN / BN / SPLIT)   // 64 key tiles per CTA
#define KC 64           // wh GEMM k-chunk
#define NKC (DIN / KC)  // 4
#define NEG_SLOPE 0.2f

// ---------------- device scratch (no allocations allowed) ----------------
__device__ __align__(16) __half g_hhi[NN * DIN];     // h hi fp16
__device__ __align__(16) __half g_hlo[NN * DIN];     // h lo fp16
__device__ __align__(16) __half g_WThi[D * DIN];     // W^T hi fp16 [n][k]
__device__ __align__(16) __half g_WTlo[D * DIN];     // W^T lo fp16
__device__ __align__(16) __half g_Kf[NN * D];        // fp16 Wh (Q and K)
__device__ __align__(16) __half g_VT[D * NN];        // V^T fp16 (dim-major)
__device__ __align__(16) float  g_Opart[SPLIT * NN * D];
__device__ float g_m[SPLIT * NN];
__device__ float g_l[SPLIT * NN];

// ---------------- warp-MMA / async-copy helpers (portable PTX) ----------------
__device__ __forceinline__ uint32_t smem_u32(const void* p) {
    uint32_t a;
    asm("{ .reg .u64 t; cvta.to.shared.u64 t, %1; cvt.u32.u64 %0, t; }" : "=r"(a) : "l"(p));
    return a;
}
__device__ __forceinline__ void ldsm4(uint32_t r[4], uint32_t addr) {
    asm volatile("ldmatrix.sync.aligned.m8n8.x4.shared.b16 {%0,%1,%2,%3}, [%4];"
                 : "=r"(r[0]), "=r"(r[1]), "=r"(r[2]), "=r"(r[3]) : "r"(addr));
}
// fp16 inputs, fp16 accumulators — 2x rate (QK^T)
__device__ __forceinline__ void mma_f16acc(uint32_t d[2], const uint32_t a[4],
                                           uint32_t b0, uint32_t b1) {
    asm volatile("mma.sync.aligned.m16n8k16.row.col.f16.f16.f16.f16 "
                 "{%0,%1}, {%2,%3,%4,%5}, {%6,%7}, {%0,%1};"
                 : "+r"(d[0]), "+r"(d[1])
                 : "r"(a[0]), "r"(a[1]), "r"(a[2]), "r"(a[3]), "r"(b0), "r"(b1));
}
// fp16 inputs, fp32 accumulators (PV, wh)
__device__ __forceinline__ void mma_f16(float d[4], const uint32_t a[4],
                                        uint32_t b0, uint32_t b1) {
    asm volatile("mma.sync.aligned.m16n8k16.row.col.f32.f16.f16.f32 "
                 "{%0,%1,%2,%3}, {%4,%5,%6,%7}, {%8,%9}, {%0,%1,%2,%3};"
                 : "+f"(d[0]), "+f"(d[1]), "+f"(d[2]), "+f"(d[3])
                 : "r"(a[0]), "r"(a[1]), "r"(a[2]), "r"(a[3]), "r"(b0), "r"(b1));
}
__device__ __forceinline__ uint32_t pack_f16x2(float lo, float hi) {
    uint32_t r;
    asm("cvt.rn.f16x2.f32 %0, %1, %2;" : "=r"(r) : "f"(hi), "f"(lo));
    return r;
}
__device__ __forceinline__ void cp16(uint32_t dst, const void* src) {
    asm volatile("cp.async.cg.shared.global [%0], [%1], 16;" :: "r"(dst), "l"(src) : "memory");
}
#define CP_COMMIT()  asm volatile("cp.async.commit_group;" ::: "memory")
#define CP_WAIT0()   asm volatile("cp.async.wait_group 0;" ::: "memory")

// attn SMEM (dynamic, 81920 B): Q 16K persistent + two 32K buffers (K+VT)
#define SM_Q       0
#define SM_BUF     16384
#define BUF_STRIDE 32768
#define BUF_K      0
#define BUF_VT     16384
#define SM_TOTAL   81920
// wh GEMM SMEM (dynamic, 131072 B): two stages of Ahi/Alo/Bhi/Blo (16K each)
#define WH_STAGE   65536
#define WH_AHI     0
#define WH_ALO     16384
#define WH_BHI     32768
#define WH_BLO     49152
#define WH_SM_TOTAL 131072

// ---------------------------------------------------------------------------
// Kernel 1a: h -> hi/lo fp16 (element-wise)
// ---------------------------------------------------------------------------
__global__ __launch_bounds__(256) void hconv_kernel(const float* __restrict__ h) {
    size_t i = ((size_t)blockIdx.x * 256 + threadIdx.x) * 4;
    float4 v = *(const float4*)&h[i];
    __half hi[4], lo[4];
    float f[4] = {v.x, v.y, v.z, v.w};
#pragma unroll
    for (int j = 0; j < 4; j++) {
        hi[j] = __float2half_rn(f[j]);
        lo[j] = __float2half_rn(f[j] - __half2float(hi[j]));
    }
    *(uint2*)&g_hhi[i] = *(uint2*)hi;
    *(uint2*)&g_hlo[i] = *(uint2*)lo;
}

// ---------------------------------------------------------------------------
// Kernel 1b: W[k][n] -> W^T hi/lo fp16 [n][k]
// ---------------------------------------------------------------------------
__global__ __launch_bounds__(256) void wconv_kernel(const float* __restrict__ W) {
    __shared__ float ts[32][33];
    const int k0 = blockIdx.x * 32;   // over DIN
    const int n0 = blockIdx.y * 32;   // over D
    const int tx = threadIdx.x, ty = threadIdx.y;   // 32 x 8
    for (int r = ty; r < 32; r += 8) ts[r][tx] = W[(size_t)(k0 + r) * D + n0 + tx];
    __syncthreads();
    for (int nn = ty; nn < 32; nn += 8) {
        float v = ts[tx][nn];         // = W[k0+tx][n0+nn]
        __half hi = __float2half_rn(v);
        __half lo = __float2half_rn(v - __half2float(hi));
        g_WThi[(size_t)(n0 + nn) * DIN + k0 + tx] = hi;
        g_WTlo[(size_t)(n0 + nn) * DIN + k0 + tx] = lo;
    }
}

// ---------------------------------------------------------------------------
// wh GEMM prefetch: one k-chunk of A(h) hi/lo [128rx64k] + B(W^T) hi/lo
// [128nx64k], 128B swizzled rows.
// ---------------------------------------------------------------------------
__device__ __forceinline__ void wh_prefetch(uint32_t sbase, int buf, int r0, int kc, int tid) {
    const uint32_t base = sbase + buf * WH_STAGE;
    const int k0 = kc * KC;
#pragma unroll
    for (int it = 0; it < 4; it++) {
        int i = tid + it * 256;
        int row = i >> 3, ch = i & 7;
        uint32_t soff = (uint32_t)(row * 128 + ((ch ^ (row & 7)) << 4));
        size_t ga = (size_t)(r0 + row) * DIN + k0 + ch * 8;
        cp16(base + WH_AHI + soff, g_hhi + ga);
        cp16(base + WH_ALO + soff, g_hlo + ga);
        size_t gb = (size_t)row * DIN + k0 + ch * 8;
        cp16(base + WH_BHI + soff, g_WThi + gb);
        cp16(base + WH_BLO + soff, g_WTlo + gb);
    }
    CP_COMMIT();
}

// ---------------------------------------------------------------------------
// Kernel 1c: Wh = h @ W on HMMA, hi/lo 3-term (fp32-grade). 64 CTAs x 128 rows.
// Outputs g_Kf (row-major fp16) and g_VT (transposed fp16).
// ---------------------------------------------------------------------------
__global__ __launch_bounds__(256, 1) void whtc_kernel() {
    extern __shared__ char smem[];
    const uint32_t sbase = smem_u32(smem);
    const int tid = threadIdx.x;
    const int wid = tid >> 5;
    const int lane = tid & 31;
    const int r0 = blockIdx.x * 128;

    wh_prefetch(sbase, 0, r0, 0, tid);

    const int arow = 16 * wid + (lane & 15);
    const int achb = lane >> 4;
    const int asw = arow & 7;
    const int brow_off = ((lane >> 4) << 3) + (lane & 7);
    const int bch_off = (lane >> 3) & 1;

    float o[16][4];
#pragma unroll
    for (int n = 0; n < 16; n++)
#pragma unroll
        for (int j = 0; j < 4; j++) o[n][j] = 0.f;

    for (int kc = 0; kc < NKC; kc++) {
        CP_WAIT0();
        __syncthreads();
        if (kc + 1 < NKC) wh_prefetch(sbase, (kc + 1) & 1, r0, kc + 1, tid);

        const uint32_t sb = sbase + (kc & 1) * WH_STAGE;
        uint32_t ahi[4][4], alo[4][4];
#pragma unroll
        for (int kt = 0; kt < 4; kt++) {
            int ch = 2 * kt + achb;
            ldsm4(ahi[kt], sb + WH_AHI + arow * 128 + ((ch ^ asw) << 4));
            ldsm4(alo[kt], sb + WH_ALO + arow * 128 + ((ch ^ asw) << 4));
        }
#pragma unroll
        for (int np = 0; np < 8; np++) {
            int brow = 16 * np + brow_off;
            int bsw = brow & 7;
            uint32_t rbh = sb + WH_BHI + brow * 128;
            uint32_t rbl = sb + WH_BLO + brow * 128;
#pragma unroll
            for (int kt = 0; kt < 4; kt++) {
                int ch = 2 * kt + bch_off;
                uint32_t sw = (uint32_t)((ch ^ bsw) << 4);
                uint32_t b[4];
                ldsm4(b, rbh + sw);
                mma_f16(o[2 * np], ahi[kt], b[0], b[1]);
                mma_f16(o[2 * np + 1], ahi[kt], b[2], b[3]);
                mma_f16(o[2 * np], alo[kt], b[0], b[1]);
                mma_f16(o[2 * np + 1], alo[kt], b[2], b[3]);
                ldsm4(b, rbl + sw);
                mma_f16(o[2 * np], ahi[kt], b[0], b[1]);
                mma_f16(o[2 * np + 1], ahi[kt], b[2], b[3]);
            }
        }
    }

    // epilogue: rows r0+16w+(lane>>2)(+8), cols 8n+2(lane&3)(+1)
    const int row = r0 + 16 * wid + (lane >> 2);
    const int cb = 2 * (lane & 3);
#pragma unroll
    for (int n = 0; n < 16; n++) {
        int c = 8 * n + cb;
        __half2 h0 = __floats2half2_rn(o[n][0], o[n][1]);
        __half2 h1 = __floats2half2_rn(o[n][2], o[n][3]);
        *(__half2*)&g_Kf[(size_t)row * D + c] = h0;
        *(__half2*)&g_Kf[(size_t)(row + 8) * D + c] = h1;
        g_VT[(size_t)c * NN + row] = __low2half(h0);
        g_VT[(size_t)(c + 1) * NN + row] = __high2half(h0);
        g_VT[(size_t)c * NN + row + 8] = __low2half(h1);
        g_VT[(size_t)(c + 1) * NN + row + 8] = __high2half(h1);
    }
}

// ---------------------------------------------------------------------------
// attn prefetch: one K/VT tile set (swizzled), 128 threads
// ---------------------------------------------------------------------------
__device__ __forceinline__ void prefetch_tile(uint32_t sbase, int buf, int key0, int tid) {
    const uint32_t base = sbase + SM_BUF + buf * BUF_STRIDE;
#pragma unroll
    for (int it = 0; it < 8; it++) {                  // K: 64 rows x 16 chunks
        int i = tid + it * 128;
        int row = i >> 4, ch = i & 15;
        cp16(base + BUF_K + row * 256 + ((ch ^ (row & 7)) << 4),
             g_Kf + (size_t)(key0 + row) * D + ch * 8);
    }
#pragma unroll
    for (int it = 0; it < 8; it++) {                  // VT: 128 rows x 8 chunks
        int i = tid + it * 128;
        int row = i >> 3, ch = i & 7;
        cp16(base + BUF_VT + (uint32_t)(row * 128 + ((ch ^ (row & 7)) << 4)),
             g_VT + (size_t)row * NN + key0 + ch * 8);
    }
    CP_COMMIT();
}

// ---------------------------------------------------------------------------
// Kernel 2: flash attention. BM=64, 128 threads (4 warps), 2 CTAs/SM.
// grid (128, SPLIT) = 256 CTAs. Warp w owns query rows q0+16w..+15.
// ---------------------------------------------------------------------------
__global__ __launch_bounds__(128, 2) void attn_kernel() {
    extern __shared__ char smem[];
    const uint32_t sbase = smem_u32(smem);
    const int tid = threadIdx.x;
    const int wid = tid >> 5;
    const int lane = tid & 31;
    const int q0 = blockIdx.x * BM;
    const int split = blockIdx.y;
    const int key_base = split * (NN / SPLIT);

    prefetch_tile(sbase, 0, key_base, tid);

    for (int i = tid; i < 1024; i += 128) {           // Q: 64 rows x 16 chunks
        int row = i >> 4, ch = i & 15;
        const uint4 v = *(const uint4*)(g_Kf + (size_t)(q0 + row) * D + ch * 8);
        *(uint4*)(smem + SM_Q + row * 256 + ((ch ^ (row & 7)) << 4)) = v;
    }
    __syncthreads();

    uint32_t qf[8][4];
    {
        int arow = 16 * wid + (lane & 15);
        int achb = lane >> 4;
#pragma unroll
        for (int k = 0; k < 8; k++) {
            int ch = 2 * k + achb;
            ldsm4(qf[k], sbase + SM_Q + arow * 256 + ((ch ^ (arow & 7)) << 4));
        }
    }

    const int brow_off = ((lane >> 4) << 3) + (lane & 7);
    const int bch_off = (lane >> 3) & 1;

    float o[16][4];
#pragma unroll
    for (int n = 0; n < 16; n++)
#pragma unroll
        for (int j = 0; j < 4; j++) o[n][j] = 0.f;
    float m0r = -1e30f, m1r = -1e30f, l0r = 0.f, l1r = 0.f;

    for (int kt = 0; kt < KT_PER; kt++) {
        CP_WAIT0();
        __syncthreads();

        const uint32_t bufb = sbase + SM_BUF + (kt & 1) * BUF_STRIDE;

        uint32_t sacc[8][2];
#pragma unroll
        for (int n = 0; n < 8; n++) { sacc[n][0] = 0u; sacc[n][1] = 0u; }
#pragma unroll
        for (int np = 0; np < 4; np++) {
            int brow = 16 * np + brow_off;
            uint32_t rbase = bufb + BUF_K + brow * 256;
            int bsw = brow & 7;
#pragma unroll
            for (int k = 0; k < 8; k++) {
                int ch = 2 * k + bch_off;
                uint32_t b[4];
                ldsm4(b, rbase + ((ch ^ bsw) << 4));
                mma_f16acc(sacc[2 * np], qf[k], b[0], b[1]);
                mma_f16acc(sacc[2 * np + 1], qf[k], b[2], b[3]);
            }
        }

        if (kt + 1 < KT_PER)
            prefetch_tile(sbase, (kt + 1) & 1, key_base + (kt + 1) * BN, tid);

        float s[8][4];
#pragma unroll
        for (int n = 0; n < 8; n++) {
            float2 x = __half22float2(*(__half2*)&sacc[n][0]);
            float2 y = __half22float2(*(__half2*)&sacc[n][1]);
            s[n][0] = x.x; s[n][1] = x.y; s[n][2] = y.x; s[n][3] = y.y;
        }

#pragma unroll
        for (int n = 0; n < 8; n++)
#pragma unroll
            for (int j = 0; j < 4; j++)
                s[n][j] = fmaxf(s[n][j], NEG_SLOPE * s[n][j]);

        float mx0 = -1e30f, mx1 = -1e30f;
#pragma unroll
        for (int n = 0; n < 8; n++) {
            mx0 = fmaxf(mx0, fmaxf(s[n][0], s[n][1]));
            mx1 = fmaxf(mx1, fmaxf(s[n][2], s[n][3]));
        }
        mx0 = fmaxf(mx0, __shfl_xor_sync(0xffffffffu, mx0, 1));
        mx0 = fmaxf(mx0, __shfl_xor_sync(0xffffffffu, mx0, 2));
        mx1 = fmaxf(mx1, __shfl_xor_sync(0xffffffffu, mx1, 1));
        mx1 = fmaxf(mx1, __shfl_xor_sync(0xffffffffu, mx1, 2));

        float mn0 = fmaxf(m0r, mx0), mn1 = fmaxf(m1r, mx1);
        float a0 = __expf(m0r - mn0), a1 = __expf(m1r - mn1);
        m0r = mn0; m1r = mn1;

        if (kt > 0) {
            unsigned need = __ballot_sync(0xffffffffu, (a0 != 1.f) || (a1 != 1.f));
            if (need) {
#pragma unroll
                for (int n = 0; n < 16; n++) {
                    o[n][0] *= a0; o[n][1] *= a0;
                    o[n][2] *= a1; o[n][3] *= a1;
                }
            }
        }

        float ps0 = 0.f, ps1 = 0.f;
#pragma unroll
        for (int n = 0; n < 8; n++) {
            s[n][0] = __expf(s[n][0] - mn0);
            s[n][1] = __expf(s[n][1] - mn0);
            s[n][2] = __expf(s[n][2] - mn1);
            s[n][3] = __expf(s[n][3] - mn1);
            ps0 += s[n][0] + s[n][1];
            ps1 += s[n][2] + s[n][3];
        }
        ps0 += __shfl_xor_sync(0xffffffffu, ps0, 1);
        ps0 += __shfl_xor_sync(0xffffffffu, ps0, 2);
        ps1 += __shfl_xor_sync(0xffffffffu, ps1, 1);
        ps1 += __shfl_xor_sync(0xffffffffu, ps1, 2);
        l0r = l0r * a0 + ps0;
        l1r = l1r * a1 + ps1;

        uint32_t pA[4][4];
#pragma unroll
        for (int j = 0; j < 4; j++) {
            pA[j][0] = pack_f16x2(s[2 * j][0], s[2 * j][1]);
            pA[j][1] = pack_f16x2(s[2 * j][2], s[2 * j][3]);
            pA[j][2] = pack_f16x2(s[2 * j + 1][0], s[2 * j + 1][1]);
            pA[j][3] = pack_f16x2(s[2 * j + 1][2], s[2 * j + 1][3]);
        }

#pragma unroll
        for (int np = 0; np < 8; np++) {
            int brow = 16 * np + brow_off;
            int bsw = brow & 7;
            uint32_t rv = bufb + BUF_VT + brow * 128;
#pragma unroll
            for (int j = 0; j < 4; j++) {
                int ch = 2 * j + bch_off;
                uint32_t b[4];
                ldsm4(b, rv + (uint32_t)((ch ^ bsw) << 4));
                mma_f16(o[2 * np], pA[j], b[0], b[1]);
                mma_f16(o[2 * np + 1], pA[j], b[2], b[3]);
            }
        }
    }

    const int r0 = q0 + 16 * wid + (lane >> 2);
    const int cb = 2 * (lane & 3);
    float* ob = &g_Opart[((size_t)split * NN + r0) * D];
#pragma unroll
    for (int n = 0; n < 16; n++) {
        *(float2*)&ob[8 * n + cb] = make_float2(o[n][0], o[n][1]);
        *(float2*)&ob[8 * D + 8 * n + cb] = make_float2(o[n][2], o[n][3]);
    }
    if ((lane & 3) == 0) {
        g_m[split * NN + r0] = m0r;
        g_l[split * NN + r0] = l0r;
        g_m[split * NN + r0 + 8] = m1r;
        g_l[split * NN + r0 + 8] = l1r;
    }
}

// ---------------------------------------------------------------------------
// Kernel 3: combine the SPLIT partials
// ---------------------------------------------------------------------------
__global__ __launch_bounds__(128) void combine_kernel(float* __restrict__ out) {
    const int r = blockIdx.x, c = threadIdx.x;
    float m0 = g_m[r], m1 = g_m[NN + r];
    float m = fmaxf(m0, m1);
    float w0 = __expf(m0 - m), w1 = __expf(m1 - m);
    float l = g_l[r] * w0 + g_l[NN + r] * w1;
    float o = g_Opart[(size_t)r * D + c] * w0 + g_Opart[(size_t)(NN + r) * D + c] * w1;
    out[(size_t)r * D + c] = o / l;
}

// ---------------------------------------------------------------------------
extern "C" void kernel_launch(void* const* d_in, const int* in_sizes, int n_in,
                              void* d_out, int out_size) {
    const float* h = (const float*)d_in[0];
    // d_in[1] = adj: unused by the math, never touched
    const float* W = (const float*)d_in[2];
    float* out = (float*)d_out;

    cudaFuncSetAttribute(attn_kernel, cudaFuncAttributeMaxDynamicSharedMemorySize, SM_TOTAL);
    cudaFuncSetAttribute(whtc_kernel, cudaFuncAttributeMaxDynamicSharedMemorySize, WH_SM_TOTAL);

    hconv_kernel<<<NN * DIN / 1024, 256>>>(h);
    wconv_kernel<<<dim3(DIN / 32, D / 32), dim3(32, 8)>>>(W);
    whtc_kernel<<<NN / 128, 256, WH_SM_TOTAL>>>();
    attn_kernel<<<dim3(NN / BM, SPLIT), 128, SM_TOTAL>>>();
    combine_kernel<<<NN, 128>>>(out);
}